// round 16
// baseline (speedup 1.0000x reference)
#include <cuda_runtime.h>
#include <cuda_bf16.h>
#include <cuda_fp16.h>
#include <math.h>
#include <stdint.h>

#define N_NODES 50000
#define N_EDGES 800000
#define HID     96
#define BM      128
#define KST     104        // bf16 elems per row; 208B stride -> LDSM conflict-free

// smem byte offsets
#define SM_AHI  0
#define SM_ALO  26624      // 128*104*2
#define SM_BHI  53248
#define SM_BLO  73216      // SM_BHI + 96*104*2
#define SM_BIAS 93184      // b1 (96 floats)
#define SM_BIAS2 93568     // b2 (96 floats)
#define SM_TOT  93952

#define WTILE_BYTES 19968            // 96*104*2
#define WMAT_BYTES  (2 * WTILE_BYTES)

// Scratch (device globals; no allocation allowed)
__device__ float  g_h[N_NODES * HID];     // gelu(x@W_pre+b) fp32
__device__ __half g_msg[N_NODES * HID];   // fp16 message accumulator (atomics)
__device__ unsigned char g_wcvt[3 * WMAT_BYTES];

// Fast GELU: erf via Abramowitz-Stegun 7.1.26 (abs err ~1e-6 in fp32). Branchless.
__device__ __forceinline__ float gelu_exact(float x) {
    float z  = x * 0.7071067811865476f;
    float az = fabsf(z);
    float t  = __fdividef(1.0f, fmaf(0.3275911f, az, 1.0f));
    float p  = fmaf(1.061405429f, t, -1.453152027f);
    p = fmaf(p, t, 1.421413741f);
    p = fmaf(p, t, -0.284496736f);
    p = fmaf(p, t, 0.254829592f);
    p = p * t;
    float e  = __expf(-az * az);
    float er = fmaf(-p, e, 1.0f);
    er = copysignf(er, z);
    return 0.5f * x * (1.0f + er);
}
__device__ __forceinline__ void bf16_split(float v, uint16_t& hi, uint16_t& lo) {
    __nv_bfloat16 h = __float2bfloat16(v);
    __nv_bfloat16 l = __float2bfloat16(v - __bfloat162float(h));
    hi = __bfloat16_as_ushort(h);
    lo = __bfloat16_as_ushort(l);
}
__device__ __forceinline__ uint32_t pack_bf16x2(float a_upper, float b_lower) {
    uint32_t d;
    asm("cvt.rn.bf16x2.f32 %0, %1, %2;" : "=r"(d) : "f"(a_upper), "f"(b_lower));
    return d;
}
__device__ __forceinline__ uint32_t smem_u32(const void* p) {
    uint32_t a;
    asm("{ .reg .u64 t; cvta.to.shared.u64 t, %1; cvt.u32.u64 %0, t; }" : "=r"(a) : "l"(p));
    return a;
}
__device__ __forceinline__ void ldsm4(uint32_t& r0, uint32_t& r1, uint32_t& r2, uint32_t& r3,
                                      uint32_t addr) {
    asm volatile("ldmatrix.sync.aligned.m8n8.x4.shared.b16 {%0,%1,%2,%3}, [%4];"
                 : "=r"(r0), "=r"(r1), "=r"(r2), "=r"(r3) : "r"(addr));
}
#define MMA_BF16(acc, a0, a1, a2, a3, b0, b1)                                    \
    asm volatile(                                                                \
        "mma.sync.aligned.m16n8k16.row.col.f32.bf16.bf16.f32 "                   \
        "{%0,%1,%2,%3}, {%4,%5,%6,%7}, {%8,%9}, {%0,%1,%2,%3};"                  \
        : "+f"((acc)[0]), "+f"((acc)[1]), "+f"((acc)[2]), "+f"((acc)[3])         \
        : "r"(a0), "r"(a1), "r"(a2), "r"(a3), "r"(b0), "r"(b1))

#define CP16(dst_u32, src_ptr)                                                   \
    asm volatile("cp.async.cg.shared.global [%0], [%1], 16;"                     \
                 :: "r"(dst_u32), "l"(src_ptr) : "memory")

// One-time W convert, parallel.
__global__ void wconv_kernel(const float* __restrict__ W0, const float* __restrict__ W1,
                             const float* __restrict__ W2) {
    const int m = blockIdx.x >> 5, s = blockIdx.x & 31;
    const float* W = (m == 0) ? W0 : (m == 1) ? W1 : W2;
    uint16_t* dhi = (uint16_t*)(g_wcvt + m * WMAT_BYTES);
    uint16_t* dlo = (uint16_t*)(g_wcvt + m * WMAT_BYTES + WTILE_BYTES);
    const int e0 = s * 288, e1 = e0 + 288;
    for (int e = e0 + threadIdx.x; e < e1; e += blockDim.x) {
        int k = e / HID, n = e - (e / HID) * HID;
        uint16_t hi, lo;
        bf16_split(W[e], hi, lo);
        dhi[n * KST + k] = hi;
        dlo[n * KST + k] = lo;
    }
}

// Shared MMA helper
struct FragOffs { uint32_t aoff[2]; uint32_t boff[3]; };
__device__ __forceinline__ void mma_pass(const uint32_t sbase, const FragOffs& fo,
                                         float acc[2][6][4]) {
#pragma unroll
    for (int ks = 0; ks < 6; ks++) {
        const uint32_t k0 = ks * 16;
        uint32_t aH[2][4], aL[2][4], bH[6][2], bL[6][2];
#pragma unroll
        for (int mt = 0; mt < 2; mt++) {
            ldsm4(aH[mt][0], aH[mt][1], aH[mt][2], aH[mt][3],
                  sbase + SM_AHI + 2 * (fo.aoff[mt] + k0));
            ldsm4(aL[mt][0], aL[mt][1], aL[mt][2], aL[mt][3],
                  sbase + SM_ALO + 2 * (fo.aoff[mt] + k0));
        }
#pragma unroll
        for (int p = 0; p < 3; p++) {
            ldsm4(bH[2 * p][0], bH[2 * p][1], bH[2 * p + 1][0], bH[2 * p + 1][1],
                  sbase + SM_BHI + 2 * (fo.boff[p] + k0));
            ldsm4(bL[2 * p][0], bL[2 * p][1], bL[2 * p + 1][0], bL[2 * p + 1][1],
                  sbase + SM_BLO + 2 * (fo.boff[p] + k0));
        }
#pragma unroll
        for (int mt = 0; mt < 2; mt++)
#pragma unroll
            for (int nt = 0; nt < 6; nt++)
                MMA_BF16(acc[mt][nt], aH[mt][0], aH[mt][1], aH[mt][2], aH[mt][3],
                         bH[nt][0], bH[nt][1]);
#pragma unroll
        for (int mt = 0; mt < 2; mt++)
#pragma unroll
            for (int nt = 0; nt < 6; nt++)
                MMA_BF16(acc[mt][nt], aH[mt][0], aH[mt][1], aH[mt][2], aH[mt][3],
                         bL[nt][0], bL[nt][1]);
#pragma unroll
        for (int mt = 0; mt < 2; mt++)
#pragma unroll
            for (int nt = 0; nt < 6; nt++)
                MMA_BF16(acc[mt][nt], aL[mt][0], aL[mt][1], aL[mt][2], aL[mt][3],
                         bH[nt][0], bH[nt][1]);
    }
}

// PRE: h = gelu(x_feat @ W_pre + b_pre); zero g_msg rows
__global__ __launch_bounds__(256, 2)
void gemm_pre(const float* __restrict__ A0,
              const unsigned char* __restrict__ wcvt,
              const float* __restrict__ bias,
              float* __restrict__ out) {
    extern __shared__ char smem[];
    uint16_t* Ahi = (uint16_t*)(smem + SM_AHI);
    uint16_t* Alo = (uint16_t*)(smem + SM_ALO);
    float*    Bsm = (float*)(smem + SM_BIAS);

    const int tid  = threadIdx.x;
    const int row0 = blockIdx.x * BM;
    const uint32_t sbase = smem_u32(smem);

    {
        const char* src = (const char*)wcvt;
#pragma unroll
        for (int i = 0; i < 10; i++) {
            int idx = tid + 256 * i;
            if (idx < WMAT_BYTES / 16) CP16(sbase + SM_BHI + 16 * idx, src + 16 * idx);
        }
        asm volatile("cp.async.commit_group;" ::: "memory");
    }
    if (tid < 24) ((float4*)Bsm)[tid] = ((const float4*)bias)[tid];

    // zero this block's g_msg rows (rows*96 halves = rows*12 float4)
    {
        int rows = N_NODES - row0; if (rows > BM) rows = BM;
        int nf4 = rows * 12;
        float4* mz = (float4*)(g_msg + (size_t)row0 * HID);
        for (int i = tid; i < nf4; i += 256)
            mz[i] = make_float4(0.f, 0.f, 0.f, 0.f);
    }

#pragma unroll
    for (int i = 0; i < 12; i++) {
        int idx4 = tid + 256 * i;
        int r = idx4 / 24, c4 = idx4 - (idx4 / 24) * 24;
        int row = row0 + r;
        float4 v = make_float4(0.f, 0.f, 0.f, 0.f);
        if (row < N_NODES)
            v = ((const float4*)(A0 + (size_t)row * HID))[c4];
        uint32_t h01 = pack_bf16x2(v.y, v.x);
        uint32_t h23 = pack_bf16x2(v.w, v.z);
        float hx = __uint_as_float(h01 << 16);
        float hy = __uint_as_float(h01 & 0xffff0000u);
        float hz = __uint_as_float(h23 << 16);
        float hw = __uint_as_float(h23 & 0xffff0000u);
        uint32_t l01 = pack_bf16x2(v.y - hy, v.x - hx);
        uint32_t l23 = pack_bf16x2(v.w - hw, v.z - hz);
        int eo = r * KST + c4 * 4;
        *(uint2*)(Ahi + eo) = make_uint2(h01, h23);
        *(uint2*)(Alo + eo) = make_uint2(l01, l23);
    }
    asm volatile("cp.async.wait_group 0;" ::: "memory");
    __syncthreads();

    const int w  = tid >> 5;
    const int l  = tid & 31;
    const int m0 = (w & 3) * 32;
    const int n0 = (w >> 2) * 48;
    FragOffs fo;
#pragma unroll
    for (int mt = 0; mt < 2; mt++)
        fo.aoff[mt] = (uint32_t)((m0 + mt * 16 + (l & 15)) * KST + (l >> 4) * 8);
#pragma unroll
    for (int p = 0; p < 3; p++)
        fo.boff[p] = (uint32_t)((n0 + p * 16 + (l >> 4) * 8 + (l & 7)) * KST + ((l >> 3) & 1) * 8);

    float acc[2][6][4];
#pragma unroll
    for (int mt = 0; mt < 2; mt++)
#pragma unroll
        for (int nt = 0; nt < 6; nt++)
#pragma unroll
            for (int q = 0; q < 4; q++) acc[mt][nt][q] = 0.f;

    mma_pass(sbase, fo, acc);

    const int lr = l >> 2;
    const int lk = 2 * (l & 3);
#pragma unroll
    for (int mt = 0; mt < 2; mt++) {
#pragma unroll
        for (int nt = 0; nt < 6; nt++) {
            int col = n0 + nt * 8 + lk;
            float bx = Bsm[col], by = Bsm[col + 1];
            int r1 = row0 + m0 + mt * 16 + lr;
            int r2 = r1 + 8;
            if (r1 < N_NODES) {
                size_t o = (size_t)r1 * HID + col;
                *(float2*)(out + o) = make_float2(gelu_exact(acc[mt][nt][0] + bx),
                                                  gelu_exact(acc[mt][nt][1] + by));
            }
            if (r2 < N_NODES) {
                size_t o = (size_t)r2 * HID + col;
                *(float2*)(out + o) = make_float2(gelu_exact(acc[mt][nt][2] + bx),
                                                  gelu_exact(acc[mt][nt][3] + by));
            }
        }
    }
}

// FFN fused: x = x_feat + msg; t = gelu(x@W1+b1); out = x + gelu(t@W2+b2)
__global__ __launch_bounds__(256, 2)
void gemm_ffn(const unsigned char* __restrict__ w1cvt,
              const unsigned char* __restrict__ w2cvt,
              const float* __restrict__ b1,
              const float* __restrict__ b2,
              const float* __restrict__ x_feat,
              float* __restrict__ out) {
    extern __shared__ char smem[];
    uint16_t* Ahi = (uint16_t*)(smem + SM_AHI);
    uint16_t* Alo = (uint16_t*)(smem + SM_ALO);
    float*    B1s = (float*)(smem + SM_BIAS);
    float*    B2s = (float*)(smem + SM_BIAS2);

    const int tid  = threadIdx.x;
    const int row0 = blockIdx.x * BM;
    const uint32_t sbase = smem_u32(smem);

    {
        const char* src = (const char*)w1cvt;
#pragma unroll
        for (int i = 0; i < 10; i++) {
            int idx = tid + 256 * i;
            if (idx < WMAT_BYTES / 16) CP16(sbase + SM_BHI + 16 * idx, src + 16 * idx);
        }
        asm volatile("cp.async.commit_group;" ::: "memory");
    }
    if (tid < 24) {
        ((float4*)B1s)[tid] = ((const float4*)b1)[tid];
        ((float4*)B2s)[tid] = ((const float4*)b2)[tid];
    }

#pragma unroll
    for (int i = 0; i < 12; i++) {
        int idx4 = tid + 256 * i;
        int r = idx4 / 24, c4 = idx4 - (idx4 / 24) * 24;
        int row = row0 + r;
        float4 v = make_float4(0.f, 0.f, 0.f, 0.f);
        if (row < N_NODES) {
            v = ((const float4*)(x_feat + (size_t)row * HID))[c4];
            uint2 mp = ((const uint2*)g_msg)[(size_t)row * 24 + c4];
            float2 m01 = __half22float2(*reinterpret_cast<__half2*>(&mp.x));
            float2 m23 = __half22float2(*reinterpret_cast<__half2*>(&mp.y));
            v.x += m01.x; v.y += m01.y; v.z += m23.x; v.w += m23.y;
        }
        uint32_t h01 = pack_bf16x2(v.y, v.x);
        uint32_t h23 = pack_bf16x2(v.w, v.z);
        float hx = __uint_as_float(h01 << 16);
        float hy = __uint_as_float(h01 & 0xffff0000u);
        float hz = __uint_as_float(h23 << 16);
        float hw = __uint_as_float(h23 & 0xffff0000u);
        uint32_t l01 = pack_bf16x2(v.y - hy, v.x - hx);
        uint32_t l23 = pack_bf16x2(v.w - hw, v.z - hz);
        int eo = r * KST + c4 * 4;
        *(uint2*)(Ahi + eo) = make_uint2(h01, h23);
        *(uint2*)(Alo + eo) = make_uint2(l01, l23);
    }
    asm volatile("cp.async.wait_group 0;" ::: "memory");
    __syncthreads();

    const int w  = tid >> 5;
    const int l  = tid & 31;
    const int m0 = (w & 3) * 32;
    const int n0 = (w >> 2) * 48;
    FragOffs fo;
#pragma unroll
    for (int mt = 0; mt < 2; mt++)
        fo.aoff[mt] = (uint32_t)((m0 + mt * 16 + (l & 15)) * KST + (l >> 4) * 8);
#pragma unroll
    for (int p = 0; p < 3; p++)
        fo.boff[p] = (uint32_t)((n0 + p * 16 + (l >> 4) * 8 + (l & 7)) * KST + ((l >> 3) & 1) * 8);

    float acc[2][6][4];
#pragma unroll
    for (int mt = 0; mt < 2; mt++)
#pragma unroll
        for (int nt = 0; nt < 6; nt++)
#pragma unroll
            for (int q = 0; q < 4; q++) acc[mt][nt][q] = 0.f;

    mma_pass(sbase, fo, acc);      // U = x @ W1

    __syncthreads();

    {
        const char* src = (const char*)w2cvt;
#pragma unroll
        for (int i = 0; i < 10; i++) {
            int idx = tid + 256 * i;
            if (idx < WMAT_BYTES / 16) CP16(sbase + SM_BHI + 16 * idx, src + 16 * idx);
        }
        asm volatile("cp.async.commit_group;" ::: "memory");
    }

    const int lr = l >> 2;
    const int lk = 2 * (l & 3);
#pragma unroll
    for (int mt = 0; mt < 2; mt++) {
#pragma unroll
        for (int nt = 0; nt < 6; nt++) {
            int col = n0 + nt * 8 + lk;
            float bx = B1s[col], by = B1s[col + 1];
            int r1 = m0 + mt * 16 + lr;
            int r2 = r1 + 8;
            float t0 = gelu_exact(acc[mt][nt][0] + bx);
            float t1 = gelu_exact(acc[mt][nt][1] + by);
            float t2 = gelu_exact(acc[mt][nt][2] + bx);
            float t3 = gelu_exact(acc[mt][nt][3] + by);
            uint32_t hA = pack_bf16x2(t1, t0);
            uint32_t hB = pack_bf16x2(t3, t2);
            float hA0 = __uint_as_float(hA << 16);
            float hA1 = __uint_as_float(hA & 0xffff0000u);
            float hB0 = __uint_as_float(hB << 16);
            float hB1 = __uint_as_float(hB & 0xffff0000u);
            uint32_t lA = pack_bf16x2(t1 - hA1, t0 - hA0);
            uint32_t lB = pack_bf16x2(t3 - hB1, t2 - hB0);
            *(uint32_t*)&Ahi[r1 * KST + col] = hA;
            *(uint32_t*)&Alo[r1 * KST + col] = lA;
            *(uint32_t*)&Ahi[r2 * KST + col] = hB;
            *(uint32_t*)&Alo[r2 * KST + col] = lB;
        }
    }
    asm volatile("cp.async.wait_group 0;" ::: "memory");
    __syncthreads();

#pragma unroll
    for (int mt = 0; mt < 2; mt++)
#pragma unroll
        for (int nt = 0; nt < 6; nt++)
#pragma unroll
            for (int q = 0; q < 4; q++) acc[mt][nt][q] = 0.f;

    mma_pass(sbase, fo, acc);      // V = t @ W2

#pragma unroll
    for (int mt = 0; mt < 2; mt++) {
#pragma unroll
        for (int nt = 0; nt < 6; nt++) {
            int col = n0 + nt * 8 + lk;
            float bx = B2s[col], by = B2s[col + 1];
            int r1 = row0 + m0 + mt * 16 + lr;
            int r2 = r1 + 8;
            if (r1 < N_NODES) {
                size_t o = (size_t)r1 * HID + col;
                float2 xv = *(const float2*)(x_feat + o);
                uint32_t mw = *(const uint32_t*)(g_msg + o);
                float2 mf = __half22float2(*reinterpret_cast<__half2*>(&mw));
                *(float2*)(out + o) =
                    make_float2(xv.x + mf.x + gelu_exact(acc[mt][nt][0] + bx),
                                xv.y + mf.y + gelu_exact(acc[mt][nt][1] + by));
            }
            if (r2 < N_NODES) {
                size_t o = (size_t)r2 * HID + col;
                float2 xv = *(const float2*)(x_feat + o);
                uint32_t mw = *(const uint32_t*)(g_msg + o);
                float2 mf = __half22float2(*reinterpret_cast<__half2*>(&mw));
                *(float2*)(out + o) =
                    make_float2(xv.x + mf.x + gelu_exact(acc[mt][nt][2] + bx),
                                xv.y + mf.y + gelu_exact(acc[mt][nt][3] + by));
            }
        }
    }
}

// Edge scatter: g_msg[dst] += h[src] * bases via f16x2 reductions (2 words/thread).
__global__ __launch_bounds__(256)
void edge_kernel(const float* __restrict__ bases,
                 const int* __restrict__ src,
                 const int* __restrict__ dst) {
    int idx = blockIdx.x * 256 + threadIdx.x;
    if (idx >= N_EDGES * 24) return;
    int e = idx / 24;
    int c = idx - e * 24;
    int s = src[e];
    int d = dst[e];
    float4 b  = ((const float4*)bases)[idx];
    float4 hv = ((const float4*)(g_h + (size_t)s * HID))[c];
    uint32_t m01, m23;
    asm("cvt.rn.f16x2.f32 %0, %1, %2;" : "=r"(m01) : "f"(b.y * hv.y), "f"(b.x * hv.x));
    asm("cvt.rn.f16x2.f32 %0, %1, %2;" : "=r"(m23) : "f"(b.w * hv.w), "f"(b.z * hv.z));
    __half* p = g_msg + (size_t)d * HID + c * 4;
    asm volatile("red.global.add.noftz.f16x2 [%0], %1;" :: "l"(p), "r"(m01) : "memory");
    asm volatile("red.global.add.noftz.f16x2 [%0], %1;" :: "l"(p + 2), "r"(m23) : "memory");
}

extern "C" void kernel_launch(void* const* d_in, const int* in_sizes, int n_in,
                              void* d_out, int out_size) {
    const float* x_feat = (const float*)d_in[0];
    const float* bases  = (const float*)d_in[1];
    const float* W_pre  = (const float*)d_in[2];
    const float* b_pre  = (const float*)d_in[3];
    const float* W1     = (const float*)d_in[4];
    const float* b1     = (const float*)d_in[5];
    const float* W2     = (const float*)d_in[6];
    const float* b2     = (const float*)d_in[7];
    const int*   src    = (const int*)d_in[8];
    const int*   dst    = (const int*)d_in[9];
    float* out = (float*)d_out;

    cudaFuncSetAttribute(gemm_pre, cudaFuncAttributeMaxDynamicSharedMemorySize, SM_TOT);
    cudaFuncSetAttribute(gemm_ffn, cudaFuncAttributeMaxDynamicSharedMemorySize, SM_TOT);

    float* g_h_p;    cudaGetSymbolAddress((void**)&g_h_p, g_h);
    unsigned char* wcvt_p; cudaGetSymbolAddress((void**)&wcvt_p, g_wcvt);

    const int gemm_grid = (N_NODES + BM - 1) / BM;   // 391
    const int edge_grid = (N_EDGES * 24 + 255) / 256;

    wconv_kernel<<<96, 256>>>(W_pre, W1, W2);
    // 1) h = gelu(x_feat @ W_pre + b_pre); g_msg = 0
    gemm_pre<<<gemm_grid, 256, SM_TOT>>>(x_feat, wcvt_p, b_pre, g_h_p);
    // 2) g_msg[dst] += h[src] * bases  (fp16 accumulation, half the atomic words)
    edge_kernel<<<edge_grid, 256>>>(bases, src, dst);
    // 3+4) x = x_feat + msg; t = gelu(x@W1+b1); out = x + gelu(t@W2+b2)
    gemm_ffn<<<gemm_grid, 256, SM_TOT>>>(wcvt_p + WMAT_BYTES, wcvt_p + 2 * WMAT_BYTES,
                                         b1, b2, x_feat, out);
}

// round 17
// speedup vs baseline: 1.5663x; 1.5663x over previous
#include <cuda_runtime.h>
#include <cuda_bf16.h>
#include <cuda_fp16.h>
#include <math.h>
#include <stdint.h>

#define N_NODES 50000
#define N_EDGES 800000
#define HID     96
#define BM      128
#define KST     104        // bf16 elems per row; 208B stride -> LDSM conflict-free

// smem byte offsets
#define SM_AHI  0
#define SM_ALO  26624      // 128*104*2
#define SM_BHI  53248
#define SM_BLO  73216      // SM_BHI + 96*104*2
#define SM_BIAS 93184      // b1 (96 floats)
#define SM_BIAS2 93568     // b2 (96 floats)
#define SM_TOT  93952

#define WTILE_BYTES 19968            // 96*104*2
#define WMAT_BYTES  (2 * WTILE_BYTES)

// Scratch (device globals; no allocation allowed)
__device__ float  g_h[N_NODES * HID];     // gelu(x@W_pre+b) fp32
__device__ __half g_msg[N_NODES * HID];   // fp16 message accumulator (atomics)
__device__ float  g_x[N_NODES * HID];     // x = x_feat + msg (built by gemm_ffn prologue)
__device__ unsigned char g_wcvt[3 * WMAT_BYTES];

// Fast GELU: erf via Abramowitz-Stegun 7.1.26 (abs err ~1e-6 in fp32). Branchless.
__device__ __forceinline__ float gelu_exact(float x) {
    float z  = x * 0.7071067811865476f;
    float az = fabsf(z);
    float t  = __fdividef(1.0f, fmaf(0.3275911f, az, 1.0f));
    float p  = fmaf(1.061405429f, t, -1.453152027f);
    p = fmaf(p, t, 1.421413741f);
    p = fmaf(p, t, -0.284496736f);
    p = fmaf(p, t, 0.254829592f);
    p = p * t;
    float e  = __expf(-az * az);
    float er = fmaf(-p, e, 1.0f);
    er = copysignf(er, z);
    return 0.5f * x * (1.0f + er);
}
__device__ __forceinline__ void bf16_split(float v, uint16_t& hi, uint16_t& lo) {
    __nv_bfloat16 h = __float2bfloat16(v);
    __nv_bfloat16 l = __float2bfloat16(v - __bfloat162float(h));
    hi = __bfloat16_as_ushort(h);
    lo = __bfloat16_as_ushort(l);
}
__device__ __forceinline__ uint32_t pack_bf16x2(float a_upper, float b_lower) {
    uint32_t d;
    asm("cvt.rn.bf16x2.f32 %0, %1, %2;" : "=r"(d) : "f"(a_upper), "f"(b_lower));
    return d;
}
__device__ __forceinline__ uint32_t pack_f16x2(float a_upper, float b_lower) {
    uint32_t d;
    asm("cvt.rn.f16x2.f32 %0, %1, %2;" : "=r"(d) : "f"(a_upper), "f"(b_lower));
    return d;
}
__device__ __forceinline__ uint32_t smem_u32(const void* p) {
    uint32_t a;
    asm("{ .reg .u64 t; cvta.to.shared.u64 t, %1; cvt.u32.u64 %0, t; }" : "=r"(a) : "l"(p));
    return a;
}
__device__ __forceinline__ void ldsm4(uint32_t& r0, uint32_t& r1, uint32_t& r2, uint32_t& r3,
                                      uint32_t addr) {
    asm volatile("ldmatrix.sync.aligned.m8n8.x4.shared.b16 {%0,%1,%2,%3}, [%4];"
                 : "=r"(r0), "=r"(r1), "=r"(r2), "=r"(r3) : "r"(addr));
}
#define MMA_BF16(acc, a0, a1, a2, a3, b0, b1)                                    \
    asm volatile(                                                                \
        "mma.sync.aligned.m16n8k16.row.col.f32.bf16.bf16.f32 "                   \
        "{%0,%1,%2,%3}, {%4,%5,%6,%7}, {%8,%9}, {%0,%1,%2,%3};"                  \
        : "+f"((acc)[0]), "+f"((acc)[1]), "+f"((acc)[2]), "+f"((acc)[3])         \
        : "r"(a0), "r"(a1), "r"(a2), "r"(a3), "r"(b0), "r"(b1))

#define CP16(dst_u32, src_ptr)                                                   \
    asm volatile("cp.async.cg.shared.global [%0], [%1], 16;"                     \
                 :: "r"(dst_u32), "l"(src_ptr) : "memory")

// One-time W convert, parallel.
__global__ void wconv_kernel(const float* __restrict__ W0, const float* __restrict__ W1,
                             const float* __restrict__ W2) {
    const int m = blockIdx.x >> 5, s = blockIdx.x & 31;
    const float* W = (m == 0) ? W0 : (m == 1) ? W1 : W2;
    uint16_t* dhi = (uint16_t*)(g_wcvt + m * WMAT_BYTES);
    uint16_t* dlo = (uint16_t*)(g_wcvt + m * WMAT_BYTES + WTILE_BYTES);
    const int e0 = s * 288, e1 = e0 + 288;
    for (int e = e0 + threadIdx.x; e < e1; e += blockDim.x) {
        int k = e / HID, n = e - (e / HID) * HID;
        uint16_t hi, lo;
        bf16_split(W[e], hi, lo);
        dhi[n * KST + k] = hi;
        dlo[n * KST + k] = lo;
    }
}

// Shared MMA helper
struct FragOffs { uint32_t aoff[2]; uint32_t boff[3]; };
__device__ __forceinline__ void mma_pass(const uint32_t sbase, const FragOffs& fo,
                                         float acc[2][6][4]) {
#pragma unroll
    for (int ks = 0; ks < 6; ks++) {
        const uint32_t k0 = ks * 16;
        uint32_t aH[2][4], aL[2][4], bH[6][2], bL[6][2];
#pragma unroll
        for (int mt = 0; mt < 2; mt++) {
            ldsm4(aH[mt][0], aH[mt][1], aH[mt][2], aH[mt][3],
                  sbase + SM_AHI + 2 * (fo.aoff[mt] + k0));
            ldsm4(aL[mt][0], aL[mt][1], aL[mt][2], aL[mt][3],
                  sbase + SM_ALO + 2 * (fo.aoff[mt] + k0));
        }
#pragma unroll
        for (int p = 0; p < 3; p++) {
            ldsm4(bH[2 * p][0], bH[2 * p][1], bH[2 * p + 1][0], bH[2 * p + 1][1],
                  sbase + SM_BHI + 2 * (fo.boff[p] + k0));
            ldsm4(bL[2 * p][0], bL[2 * p][1], bL[2 * p + 1][0], bL[2 * p + 1][1],
                  sbase + SM_BLO + 2 * (fo.boff[p] + k0));
        }
#pragma unroll
        for (int mt = 0; mt < 2; mt++)
#pragma unroll
            for (int nt = 0; nt < 6; nt++)
                MMA_BF16(acc[mt][nt], aH[mt][0], aH[mt][1], aH[mt][2], aH[mt][3],
                         bH[nt][0], bH[nt][1]);
#pragma unroll
        for (int mt = 0; mt < 2; mt++)
#pragma unroll
            for (int nt = 0; nt < 6; nt++)
                MMA_BF16(acc[mt][nt], aH[mt][0], aH[mt][1], aH[mt][2], aH[mt][3],
                         bL[nt][0], bL[nt][1]);
#pragma unroll
        for (int mt = 0; mt < 2; mt++)
#pragma unroll
            for (int nt = 0; nt < 6; nt++)
                MMA_BF16(acc[mt][nt], aL[mt][0], aL[mt][1], aL[mt][2], aL[mt][3],
                         bH[nt][0], bH[nt][1]);
    }
}

// PRE: h = gelu(x_feat @ W_pre + b_pre); zero g_msg rows
__global__ __launch_bounds__(256, 2)
void gemm_pre(const float* __restrict__ A0,
              const unsigned char* __restrict__ wcvt,
              const float* __restrict__ bias,
              float* __restrict__ out) {
    extern __shared__ char smem[];
    uint16_t* Ahi = (uint16_t*)(smem + SM_AHI);
    uint16_t* Alo = (uint16_t*)(smem + SM_ALO);
    float*    Bsm = (float*)(smem + SM_BIAS);

    const int tid  = threadIdx.x;
    const int row0 = blockIdx.x * BM;
    const uint32_t sbase = smem_u32(smem);

    {
        const char* src = (const char*)wcvt;
#pragma unroll
        for (int i = 0; i < 10; i++) {
            int idx = tid + 256 * i;
            if (idx < WMAT_BYTES / 16) CP16(sbase + SM_BHI + 16 * idx, src + 16 * idx);
        }
        asm volatile("cp.async.commit_group;" ::: "memory");
    }
    if (tid < 24) ((float4*)Bsm)[tid] = ((const float4*)bias)[tid];

    // zero this block's g_msg rows
    {
        int rows = N_NODES - row0; if (rows > BM) rows = BM;
        int nf4 = rows * 12;
        float4* mz = (float4*)(g_msg + (size_t)row0 * HID);
        for (int i = tid; i < nf4; i += 256)
            mz[i] = make_float4(0.f, 0.f, 0.f, 0.f);
    }

#pragma unroll
    for (int i = 0; i < 12; i++) {
        int idx4 = tid + 256 * i;
        int r = idx4 / 24, c4 = idx4 - (idx4 / 24) * 24;
        int row = row0 + r;
        float4 v = make_float4(0.f, 0.f, 0.f, 0.f);
        if (row < N_NODES)
            v = ((const float4*)(A0 + (size_t)row * HID))[c4];
        uint32_t h01 = pack_bf16x2(v.y, v.x);
        uint32_t h23 = pack_bf16x2(v.w, v.z);
        float hx = __uint_as_float(h01 << 16);
        float hy = __uint_as_float(h01 & 0xffff0000u);
        float hz = __uint_as_float(h23 << 16);
        float hw = __uint_as_float(h23 & 0xffff0000u);
        uint32_t l01 = pack_bf16x2(v.y - hy, v.x - hx);
        uint32_t l23 = pack_bf16x2(v.w - hw, v.z - hz);
        int eo = r * KST + c4 * 4;
        *(uint2*)(Ahi + eo) = make_uint2(h01, h23);
        *(uint2*)(Alo + eo) = make_uint2(l01, l23);
    }
    asm volatile("cp.async.wait_group 0;" ::: "memory");
    __syncthreads();

    const int w  = tid >> 5;
    const int l  = tid & 31;
    const int m0 = (w & 3) * 32;
    const int n0 = (w >> 2) * 48;
    FragOffs fo;
#pragma unroll
    for (int mt = 0; mt < 2; mt++)
        fo.aoff[mt] = (uint32_t)((m0 + mt * 16 + (l & 15)) * KST + (l >> 4) * 8);
#pragma unroll
    for (int p = 0; p < 3; p++)
        fo.boff[p] = (uint32_t)((n0 + p * 16 + (l >> 4) * 8 + (l & 7)) * KST + ((l >> 3) & 1) * 8);

    float acc[2][6][4];
#pragma unroll
    for (int mt = 0; mt < 2; mt++)
#pragma unroll
        for (int nt = 0; nt < 6; nt++)
#pragma unroll
            for (int q = 0; q < 4; q++) acc[mt][nt][q] = 0.f;

    mma_pass(sbase, fo, acc);

    const int lr = l >> 2;
    const int lk = 2 * (l & 3);
#pragma unroll
    for (int mt = 0; mt < 2; mt++) {
#pragma unroll
        for (int nt = 0; nt < 6; nt++) {
            int col = n0 + nt * 8 + lk;
            float bx = Bsm[col], by = Bsm[col + 1];
            int r1 = row0 + m0 + mt * 16 + lr;
            int r2 = r1 + 8;
            if (r1 < N_NODES) {
                size_t o = (size_t)r1 * HID + col;
                *(float2*)(out + o) = make_float2(gelu_exact(acc[mt][nt][0] + bx),
                                                  gelu_exact(acc[mt][nt][1] + by));
            }
            if (r2 < N_NODES) {
                size_t o = (size_t)r2 * HID + col;
                *(float2*)(out + o) = make_float2(gelu_exact(acc[mt][nt][2] + bx),
                                                  gelu_exact(acc[mt][nt][3] + by));
            }
        }
    }
}

// FFN fused: x = x_feat + msg (persisted to g_x); t = gelu(x@W1+b1);
//            out = g_x + gelu(t@W2+b2)
__global__ __launch_bounds__(256, 2)
void gemm_ffn(const unsigned char* __restrict__ w1cvt,
              const unsigned char* __restrict__ w2cvt,
              const float* __restrict__ b1,
              const float* __restrict__ b2,
              const float* __restrict__ x_feat,
              float* __restrict__ out) {
    extern __shared__ char smem[];
    uint16_t* Ahi = (uint16_t*)(smem + SM_AHI);
    uint16_t* Alo = (uint16_t*)(smem + SM_ALO);
    float*    B1s = (float*)(smem + SM_BIAS);
    float*    B2s = (float*)(smem + SM_BIAS2);

    const int tid  = threadIdx.x;
    const int row0 = blockIdx.x * BM;
    const uint32_t sbase = smem_u32(smem);

    {
        const char* src = (const char*)w1cvt;
#pragma unroll
        for (int i = 0; i < 10; i++) {
            int idx = tid + 256 * i;
            if (idx < WMAT_BYTES / 16) CP16(sbase + SM_BHI + 16 * idx, src + 16 * idx);
        }
        asm volatile("cp.async.commit_group;" ::: "memory");
    }
    if (tid < 24) {
        ((float4*)B1s)[tid] = ((const float4*)b1)[tid];
        ((float4*)B2s)[tid] = ((const float4*)b2)[tid];
    }

    // x = x_feat + msg; persist to g_x (coalesced); convert to bf16 split tiles
#pragma unroll
    for (int i = 0; i < 12; i++) {
        int idx4 = tid + 256 * i;
        int r = idx4 / 24, c4 = idx4 - (idx4 / 24) * 24;
        int row = row0 + r;
        float4 v = make_float4(0.f, 0.f, 0.f, 0.f);
        if (row < N_NODES) {
            v = ((const float4*)(x_feat + (size_t)row * HID))[c4];
            uint2 mp = ((const uint2*)g_msg)[(size_t)row * 24 + c4];
            float2 m01 = __half22float2(*reinterpret_cast<__half2*>(&mp.x));
            float2 m23 = __half22float2(*reinterpret_cast<__half2*>(&mp.y));
            v.x += m01.x; v.y += m01.y; v.z += m23.x; v.w += m23.y;
            ((float4*)(g_x + (size_t)row * HID))[c4] = v;
        }
        uint32_t h01 = pack_bf16x2(v.y, v.x);
        uint32_t h23 = pack_bf16x2(v.w, v.z);
        float hx = __uint_as_float(h01 << 16);
        float hy = __uint_as_float(h01 & 0xffff0000u);
        float hz = __uint_as_float(h23 << 16);
        float hw = __uint_as_float(h23 & 0xffff0000u);
        uint32_t l01 = pack_bf16x2(v.y - hy, v.x - hx);
        uint32_t l23 = pack_bf16x2(v.w - hw, v.z - hz);
        int eo = r * KST + c4 * 4;
        *(uint2*)(Ahi + eo) = make_uint2(h01, h23);
        *(uint2*)(Alo + eo) = make_uint2(l01, l23);
    }
    asm volatile("cp.async.wait_group 0;" ::: "memory");
    __syncthreads();

    const int w  = tid >> 5;
    const int l  = tid & 31;
    const int m0 = (w & 3) * 32;
    const int n0 = (w >> 2) * 48;
    FragOffs fo;
#pragma unroll
    for (int mt = 0; mt < 2; mt++)
        fo.aoff[mt] = (uint32_t)((m0 + mt * 16 + (l & 15)) * KST + (l >> 4) * 8);
#pragma unroll
    for (int p = 0; p < 3; p++)
        fo.boff[p] = (uint32_t)((n0 + p * 16 + (l >> 4) * 8 + (l & 7)) * KST + ((l >> 3) & 1) * 8);

    float acc[2][6][4];
#pragma unroll
    for (int mt = 0; mt < 2; mt++)
#pragma unroll
        for (int nt = 0; nt < 6; nt++)
#pragma unroll
            for (int q = 0; q < 4; q++) acc[mt][nt][q] = 0.f;

    mma_pass(sbase, fo, acc);      // U = x @ W1

    __syncthreads();

    {
        const char* src = (const char*)w2cvt;
#pragma unroll
        for (int i = 0; i < 10; i++) {
            int idx = tid + 256 * i;
            if (idx < WMAT_BYTES / 16) CP16(sbase + SM_BHI + 16 * idx, src + 16 * idx);
        }
        asm volatile("cp.async.commit_group;" ::: "memory");
    }

    const int lr = l >> 2;
    const int lk = 2 * (l & 3);
#pragma unroll
    for (int mt = 0; mt < 2; mt++) {
#pragma unroll
        for (int nt = 0; nt < 6; nt++) {
            int col = n0 + nt * 8 + lk;
            float bx = B1s[col], by = B1s[col + 1];
            int r1 = m0 + mt * 16 + lr;
            int r2 = r1 + 8;
            float t0 = gelu_exact(acc[mt][nt][0] + bx);
            float t1 = gelu_exact(acc[mt][nt][1] + by);
            float t2 = gelu_exact(acc[mt][nt][2] + bx);
            float t3 = gelu_exact(acc[mt][nt][3] + by);
            uint32_t hA = pack_bf16x2(t1, t0);
            uint32_t hB = pack_bf16x2(t3, t2);
            float hA0 = __uint_as_float(hA << 16);
            float hA1 = __uint_as_float(hA & 0xffff0000u);
            float hB0 = __uint_as_float(hB << 16);
            float hB1 = __uint_as_float(hB & 0xffff0000u);
            uint32_t lA = pack_bf16x2(t1 - hA1, t0 - hA0);
            uint32_t lB = pack_bf16x2(t3 - hB1, t2 - hB0);
            *(uint32_t*)&Ahi[r1 * KST + col] = hA;
            *(uint32_t*)&Alo[r1 * KST + col] = lA;
            *(uint32_t*)&Ahi[r2 * KST + col] = hB;
            *(uint32_t*)&Alo[r2 * KST + col] = lB;
        }
    }
    asm volatile("cp.async.wait_group 0;" ::: "memory");
    __syncthreads();

#pragma unroll
    for (int mt = 0; mt < 2; mt++)
#pragma unroll
        for (int nt = 0; nt < 6; nt++)
#pragma unroll
            for (int q = 0; q < 4; q++) acc[mt][nt][q] = 0.f;

    mma_pass(sbase, fo, acc);      // V = t @ W2

#pragma unroll
    for (int mt = 0; mt < 2; mt++) {
#pragma unroll
        for (int nt = 0; nt < 6; nt++) {
            int col = n0 + nt * 8 + lk;
            float bx = B2s[col], by = B2s[col + 1];
            int r1 = row0 + m0 + mt * 16 + lr;
            int r2 = r1 + 8;
            if (r1 < N_NODES) {
                size_t o = (size_t)r1 * HID + col;
                float2 xv = *(const float2*)(g_x + o);
                *(float2*)(out + o) = make_float2(xv.x + gelu_exact(acc[mt][nt][0] + bx),
                                                  xv.y + gelu_exact(acc[mt][nt][1] + by));
            }
            if (r2 < N_NODES) {
                size_t o = (size_t)r2 * HID + col;
                float2 xv = *(const float2*)(g_x + o);
                *(float2*)(out + o) = make_float2(xv.x + gelu_exact(acc[mt][nt][2] + bx),
                                                  xv.y + gelu_exact(acc[mt][nt][3] + by));
            }
        }
    }
}

// Edge scatter: g_msg[dst] += h[src] * bases.
// One thread per 8 columns: one red.global.add.noftz.v4.f16x2 (8 halves / lane-op).
__global__ __launch_bounds__(256)
void edge_kernel(const float* __restrict__ bases,
                 const int* __restrict__ src,
                 const int* __restrict__ dst) {
    int idx = blockIdx.x * 256 + threadIdx.x;           // < 9.6M
    if (idx >= N_EDGES * 12) return;
    int e = idx / 12;
    int c8 = idx - e * 12;                              // 8-column group
    int s = src[e];
    int d = dst[e];
    const float4* b4 = (const float4*)bases + (size_t)e * 24 + c8 * 2;
    const float4* h4 = (const float4*)(g_h + (size_t)s * HID) + c8 * 2;
    float4 b0 = b4[0], b1 = b4[1];
    float4 h0 = h4[0], h1 = h4[1];
    uint32_t r0 = pack_f16x2(b0.y * h0.y, b0.x * h0.x);
    uint32_t r1 = pack_f16x2(b0.w * h0.w, b0.z * h0.z);
    uint32_t r2 = pack_f16x2(b1.y * h1.y, b1.x * h1.x);
    uint32_t r3 = pack_f16x2(b1.w * h1.w, b1.z * h1.z);
    __half* p = g_msg + (size_t)d * HID + c8 * 8;
    asm volatile("red.global.add.noftz.v4.f16x2 [%0], {%1, %2, %3, %4};"
                 :: "l"(p), "r"(r0), "r"(r1), "r"(r2), "r"(r3) : "memory");
}

extern "C" void kernel_launch(void* const* d_in, const int* in_sizes, int n_in,
                              void* d_out, int out_size) {
    const float* x_feat = (const float*)d_in[0];
    const float* bases  = (const float*)d_in[1];
    const float* W_pre  = (const float*)d_in[2];
    const float* b_pre  = (const float*)d_in[3];
    const float* W1     = (const float*)d_in[4];
    const float* b1     = (const float*)d_in[5];
    const float* W2     = (const float*)d_in[6];
    const float* b2     = (const float*)d_in[7];
    const int*   src    = (const int*)d_in[8];
    const int*   dst    = (const int*)d_in[9];
    float* out = (float*)d_out;

    cudaFuncSetAttribute(gemm_pre, cudaFuncAttributeMaxDynamicSharedMemorySize, SM_TOT);
    cudaFuncSetAttribute(gemm_ffn, cudaFuncAttributeMaxDynamicSharedMemorySize, SM_TOT);

    float* g_h_p;    cudaGetSymbolAddress((void**)&g_h_p, g_h);
    unsigned char* wcvt_p; cudaGetSymbolAddress((void**)&wcvt_p, g_wcvt);

    const int gemm_grid = (N_NODES + BM - 1) / BM;   // 391
    const int edge_grid = (N_EDGES * 12 + 255) / 256;

    wconv_kernel<<<96, 256>>>(W_pre, W1, W2);
    // 1) h = gelu(x_feat @ W_pre + b_pre); g_msg = 0
    gemm_pre<<<gemm_grid, 256, SM_TOT>>>(x_feat, wcvt_p, b_pre, g_h_p);
    // 2) g_msg[dst] += h[src] * bases  (v4.f16x2: half the REDG lane-ops)
    edge_kernel<<<edge_grid, 256>>>(bases, src, dst);
    // 3+4) x = x_feat + msg (persisted); t = gelu(x@W1+b1); out = x + gelu(t@W2+b2)
    gemm_ffn<<<gemm_grid, 256, SM_TOT>>>(wcvt_p + WMAT_BYTES, wcvt_p + 2 * WMAT_BYTES,
                                         b1, b2, x_feat, out);
}